// round 9
// baseline (speedup 1.0000x reference)
#include <cuda_runtime.h>
#include <math.h>

#define N_MAX   200000
#define E_MAX   3200000
#define D       25
#define STRIDE  32
#define CAP     64         // fixed CSR capacity per node (Poisson(16): P(deg>=64) ~ 1e-17)
#define EPS     1e-5f

// ---------------- scratch (device globals; no allocation allowed) -----------
__device__ __align__(16) float g_hw[N_MAX * STRIDE];   // dinv-scaled h@W messages
__device__ __align__(16) float g_pre[N_MAX * STRIDE];  // pre-batchnorm activations
__device__ __align__(16) int   g_csr[N_MAX * CAP];     // fixed-capacity per-dst neighbor lists (51MB)
__device__ int   g_cur[N_MAX];       // fill cursor == in-degree after k_fill
__device__ float g_dinv[N_MAX];
__device__ float g_stats[256];       // L1 @0: [0:25)=sum [32:57)=sumsq ; L2 @128

// ---------------- kernels ---------------------------------------------------

__global__ void k_zero(int n) {
    int i = blockIdx.x * blockDim.x + threadIdx.x;
    if (i < n)   g_cur[i] = 0;
    if (i < 256) g_stats[i] = 0.f;
}

// one-pass CSR build: 8 edges per thread, int4 index reads, 8 atomics in flight
__global__ void k_fill(const int* __restrict__ ei, int E) {
    int t = blockIdx.x * blockDim.x + threadIdx.x;
    int e = t * 8;
    if (e + 7 < E) {
        int4 s0 = *(const int4*)(ei + e);
        int4 s1 = *(const int4*)(ei + e + 4);
        int4 d0 = *(const int4*)(ei + E + e);
        int4 d1 = *(const int4*)(ei + E + e + 4);
        int p0 = atomicAdd(&g_cur[d0.x], 1);
        int p1 = atomicAdd(&g_cur[d0.y], 1);
        int p2 = atomicAdd(&g_cur[d0.z], 1);
        int p3 = atomicAdd(&g_cur[d0.w], 1);
        int p4 = atomicAdd(&g_cur[d1.x], 1);
        int p5 = atomicAdd(&g_cur[d1.y], 1);
        int p6 = atomicAdd(&g_cur[d1.z], 1);
        int p7 = atomicAdd(&g_cur[d1.w], 1);
        g_csr[d0.x * CAP + p0] = s0.x;
        g_csr[d0.y * CAP + p1] = s0.y;
        g_csr[d0.z * CAP + p2] = s0.z;
        g_csr[d0.w * CAP + p3] = s0.w;
        g_csr[d1.x * CAP + p4] = s1.x;
        g_csr[d1.y * CAP + p5] = s1.y;
        g_csr[d1.z * CAP + p6] = s1.z;
        g_csr[d1.w * CAP + p7] = s1.w;
    } else {
        for (; e < E; e++) {
            int sv = ei[e];
            int dv = ei[E + e];
            int p = atomicAdd(&g_cur[dv], 1);
            g_csr[dv * CAP + p] = sv;
        }
    }
}

// gather emb[x], h@W1, scale by dinv[node] (deg = g_cur after fill)
__global__ void k_node1(const int* __restrict__ x, const float* __restrict__ emb,
                        const float* __restrict__ W, int n) {
    __shared__ float ws[D * STRIDE];
    for (int i = threadIdx.x; i < D * STRIDE; i += blockDim.x) {
        int k = i / STRIDE, f = i % STRIDE;
        ws[i] = (f < D) ? W[k * D + f] : 0.f;
    }
    __syncthreads();
    int lane = threadIdx.x & 31;
    int node = blockIdx.x * (blockDim.x >> 5) + (threadIdx.x >> 5);
    if (node >= n) return;

    float dinv = rsqrtf((float)(g_cur[node] + 1));
    if (lane == 0) g_dinv[node] = dinv;

    int xi = x[node];
    float h = (lane < D) ? emb[xi * D + lane] : 0.f;

    float acc = 0.f;
#pragma unroll
    for (int k = 0; k < D; k++) {
        float hk = __shfl_sync(0xffffffffu, h, k);
        acc = fmaf(hk, ws[k * STRIDE + lane], acc);
    }
    g_hw[node * STRIDE + lane] = (lane < D) ? acc * dinv : 0.f;
}

// warp-per-node gather aggregation: lane = feature, scalar accumulation,
// int4 broadcast index loads, 8 value loads in flight, no intra-warp divergence.
__global__ void __launch_bounds__(256, 8) k_agg(const float* __restrict__ b, int off, int n) {
    __shared__ float ssum[32], ssq[32];
    if (threadIdx.x < 32) { ssum[threadIdx.x] = 0.f; ssq[threadIdx.x] = 0.f; }
    __syncthreads();

    int lane = threadIdx.x & 31;
    int warp = threadIdx.x >> 5;
    int wpb  = blockDim.x >> 5;
    float bf = (lane < D) ? b[lane] : 0.f;
    float psum = 0.f, psq = 0.f;

    for (int node = blockIdx.x * wpb + warp; node < n; node += gridDim.x * wpb) {
        const int4* r4 = (const int4*)&g_csr[node * CAP];
        int cnt = g_cur[node];
        float a0 = g_hw[node * STRIDE + lane];   // self-loop term
        float a1 = 0.f;
        int j = 0;
        for (; j + 8 <= cnt; j += 8) {
            int4 iA = __ldg(&r4[j >> 2]);
            int4 iB = __ldg(&r4[(j >> 2) + 1]);
            float v0 = g_hw[iA.x * STRIDE + lane];
            float v1 = g_hw[iA.y * STRIDE + lane];
            float v2 = g_hw[iA.z * STRIDE + lane];
            float v3 = g_hw[iA.w * STRIDE + lane];
            float v4 = g_hw[iB.x * STRIDE + lane];
            float v5 = g_hw[iB.y * STRIDE + lane];
            float v6 = g_hw[iB.z * STRIDE + lane];
            float v7 = g_hw[iB.w * STRIDE + lane];
            a0 += (v0 + v1) + (v2 + v3);
            a1 += (v4 + v5) + (v6 + v7);
        }
        if (j + 4 <= cnt) {
            int4 iA = __ldg(&r4[j >> 2]);
            float v0 = g_hw[iA.x * STRIDE + lane];
            float v1 = g_hw[iA.y * STRIDE + lane];
            float v2 = g_hw[iA.z * STRIDE + lane];
            float v3 = g_hw[iA.w * STRIDE + lane];
            a0 += (v0 + v1) + (v2 + v3);
            j += 4;
        }
        const int* row = (const int*)r4;
        for (; j < cnt; j++) {
            a1 += g_hw[__ldg(row + j) * STRIDE + lane];
        }
        float dinv = g_dinv[node];
        float v = fmaf(a0 + a1, dinv, bf);
        g_pre[node * STRIDE + lane] = v;
        psum += v;
        psq  = fmaf(v, v, psq);
    }

    atomicAdd(&ssum[lane], psum);
    atomicAdd(&ssq[lane],  psq);
    __syncthreads();
    if (threadIdx.x < D) {
        atomicAdd(&g_stats[off + threadIdx.x],      ssum[threadIdx.x]);
        atomicAdd(&g_stats[off + 32 + threadIdx.x], ssq[threadIdx.x]);
    }
}

// bn+relu of layer-1 output (inline stats), then h@W2, scale by dinv
__global__ void k_node2(const float* __restrict__ W, const float* __restrict__ g,
                        const float* __restrict__ be, int off, float inv_n, int n) {
    __shared__ float ws[D * STRIDE];
    for (int i = threadIdx.x; i < D * STRIDE; i += blockDim.x) {
        int k = i / STRIDE, f = i % STRIDE;
        ws[i] = (f < D) ? W[k * D + f] : 0.f;
    }
    __syncthreads();
    int lane = threadIdx.x & 31;
    int node = blockIdx.x * (blockDim.x >> 5) + (threadIdx.x >> 5);
    if (node >= n) return;

    float h = 0.f;
    if (lane < D) {
        float mu  = g_stats[off + lane] * inv_n;
        float var = g_stats[off + 32 + lane] * inv_n - mu * mu;
        float rs  = rsqrtf(var + EPS);
        float pre = g_pre[node * STRIDE + lane];
        float t = (pre - mu) * rs * g[lane] + be[lane];
        h = fmaxf(t, 0.f);
    }
    float acc = 0.f;
#pragma unroll
    for (int k = 0; k < D; k++) {
        float hk = __shfl_sync(0xffffffffu, h, k);
        acc = fmaf(hk, ws[k * STRIDE + lane], acc);
    }
    float dinv = g_dinv[node];
    g_hw[node * STRIDE + lane] = (lane < D) ? acc * dinv : 0.f;
}

// bn+relu of layer-2 output (inline stats), MLP head (25->12 relu ->1), sigmoid
__global__ void k_final(const float* __restrict__ g, const float* __restrict__ be,
                        const float* __restrict__ Wm1, const float* __restrict__ bm1,
                        const float* __restrict__ Wm2, const float* __restrict__ bm2,
                        float* __restrict__ out, int off, float inv_n, int n) {
    __shared__ float wm[D * 16];
    for (int i = threadIdx.x; i < D * 16; i += blockDim.x) {
        int f = i >> 4, j = i & 15;
        wm[i] = (j < 12) ? Wm1[f * 12 + j] : 0.f;
    }
    __syncthreads();
    int lane = threadIdx.x & 31;
    int node = blockIdx.x * (blockDim.x >> 5) + (threadIdx.x >> 5);
    if (node >= n) return;

    float h = 0.f;
    if (lane < D) {
        float mu  = g_stats[off + lane] * inv_n;
        float var = g_stats[off + 32 + lane] * inv_n - mu * mu;
        float rs  = rsqrtf(var + EPS);
        float pre = g_pre[node * STRIDE + lane];
        float t = (pre - mu) * rs * g[lane] + be[lane];
        h = fmaxf(t, 0.f);
    }
    float m = 0.f;
#pragma unroll
    for (int f = 0; f < D; f++) {
        float hf = __shfl_sync(0xffffffffu, h, f);
        float w  = (lane < 16) ? wm[f * 16 + lane] : 0.f;
        m = fmaf(hf, w, m);
    }
    float t = 0.f;
    if (lane < 12) {
        m = fmaxf(m + bm1[lane], 0.f);
        t = m * Wm2[lane];
    }
#pragma unroll
    for (int o = 16; o > 0; o >>= 1) t += __shfl_down_sync(0xffffffffu, t, o);
    if (lane == 0) {
        float z = t + bm2[0];
        out[node] = 1.f / (1.f + __expf(-z));
    }
}

// ---------------- launch -----------------------------------------------------

extern "C" void kernel_launch(void* const* d_in, const int* in_sizes, int n_in,
                              void* d_out, int out_size) {
    const int*   x   = (const int*)d_in[0];
    const int*   ei  = (const int*)d_in[1];
    const float* emb = (const float*)d_in[2];
    const float* W1  = (const float*)d_in[3];
    const float* b1  = (const float*)d_in[4];
    const float* g1  = (const float*)d_in[5];
    const float* be1 = (const float*)d_in[6];
    const float* W2  = (const float*)d_in[7];
    const float* b2  = (const float*)d_in[8];
    const float* g2  = (const float*)d_in[9];
    const float* be2 = (const float*)d_in[10];
    const float* Wm1 = (const float*)d_in[11];
    const float* bm1 = (const float*)d_in[12];
    const float* Wm2 = (const float*)d_in[13];
    const float* bm2 = (const float*)d_in[14];
    float* out = (float*)d_out;

    int n = in_sizes[0];
    int E = in_sizes[1] / 2;
    float inv_n = 1.f / (float)n;

    int zb = (n + 255) / 256;
    int eb8 = ((E + 7) / 8 + 255) / 256;   // 8 edges/thread
    int nodeBlocks = (n + 7) / 8;          // 8 warps/block, 1 node/warp

    k_zero<<<zb, 256>>>(n);
    k_fill<<<eb8, 256>>>(ei, E);

    k_node1<<<nodeBlocks, 256>>>(x, emb, W1, n);
    k_agg<<<1184, 256>>>(b1, 0, n);

    k_node2<<<nodeBlocks, 256>>>(W2, g1, be1, 0, inv_n, n);
    k_agg<<<1184, 256>>>(b2, 128, n);

    k_final<<<nodeBlocks, 256>>>(g2, be2, Wm1, bm1, Wm2, bm2, out, 128, inv_n, n);
}

// round 11
// speedup vs baseline: 1.3052x; 1.3052x over previous
#include <cuda_runtime.h>
#include <math.h>

#define N_MAX   200000
#define E_MAX   3200000
#define D       25
#define STRIDE  32
#define CAP     64         // fixed CSR capacity per node (Poisson(16): P(deg>=64) ~ 1e-17)
#define EPS     1e-5f

// ---------------- scratch (device globals; no allocation allowed) -----------
__device__ __align__(16) float g_hw[N_MAX * STRIDE];   // dinv-scaled h@W messages
__device__ __align__(16) float g_pre[N_MAX * STRIDE];  // pre-batchnorm activations
__device__ __align__(16) int   g_csr[N_MAX * CAP];     // fixed-capacity per-dst neighbor lists (51MB)
__device__ int   g_cur[N_MAX];       // fill cursor == in-degree; reset to 0 by k_final each launch
__device__ float g_dinv[N_MAX];
__device__ float g_stats[256];       // L1 @0: [0:25)=sum [32:57)=sumsq ; L2 @128; reset by k_fill

// ---------------- kernels ---------------------------------------------------

// one-pass CSR build: 4 edges per thread; block 0 also re-zeros g_stats
__global__ void k_fill(const int* __restrict__ ei, int E) {
    if (blockIdx.x == 0 && threadIdx.x < 256) g_stats[threadIdx.x] = 0.f;
    int t = blockIdx.x * blockDim.x + threadIdx.x;
    int e = t * 4;
    if (e + 3 < E) {
        int4 s = *(const int4*)(ei + e);
        int4 d = *(const int4*)(ei + E + e);
        int p0 = atomicAdd(&g_cur[d.x], 1);
        int p1 = atomicAdd(&g_cur[d.y], 1);
        int p2 = atomicAdd(&g_cur[d.z], 1);
        int p3 = atomicAdd(&g_cur[d.w], 1);
        g_csr[d.x * CAP + p0] = s.x;
        g_csr[d.y * CAP + p1] = s.y;
        g_csr[d.z * CAP + p2] = s.z;
        g_csr[d.w * CAP + p3] = s.w;
    } else {
        for (; e < E; e++) {
            int sv = ei[e];
            int dv = ei[E + e];
            int p = atomicAdd(&g_cur[dv], 1);
            g_csr[dv * CAP + p] = sv;
        }
    }
}

// gather emb[x], h@W1 (W column register-resident), scale by dinv
__global__ void k_node1(const int* __restrict__ x, const float* __restrict__ emb,
                        const float* __restrict__ W, int n) {
    int lane = threadIdx.x & 31;
    int warp = threadIdx.x >> 5;
    int wpb  = blockDim.x >> 5;
    float wcol[D];
#pragma unroll
    for (int k = 0; k < D; k++) wcol[k] = (lane < D) ? W[k * D + lane] : 0.f;

    for (int node = blockIdx.x * wpb + warp; node < n; node += gridDim.x * wpb) {
        float dinv = rsqrtf((float)(g_cur[node] + 1));
        if (lane == 0) g_dinv[node] = dinv;
        int xi = x[node];
        float h = (lane < D) ? __ldg(&emb[xi * D + lane]) : 0.f;
        float acc = 0.f;
#pragma unroll
        for (int k = 0; k < D; k++)
            acc = fmaf(__shfl_sync(0xffffffffu, h, k), wcol[k], acc);
        g_hw[node * STRIDE + lane] = (lane < D) ? acc * dinv : 0.f;
    }
}

// gather aggregation: 8 threads per node, float4 per thread, unroll 8 (2 acc sets)
__global__ void k_agg(const float* __restrict__ b, int off, int n) {
    __shared__ float sb[32];
    __shared__ float ssum[32], ssq[32];
    if (threadIdx.x < 32) {
        sb[threadIdx.x]   = (threadIdx.x < D) ? b[threadIdx.x] : 0.f;
        ssum[threadIdx.x] = 0.f;
        ssq[threadIdx.x]  = 0.f;
    }
    __syncthreads();

    int sub = threadIdx.x & 7;        // float4 slot within row
    int grp = threadIdx.x >> 3;       // node slot within block
    int gpb = blockDim.x >> 3;
    const float4* base = (const float4*)g_hw;
    float4* preb = (float4*)g_pre;
    float4 bf = ((const float4*)sb)[sub];
    float4 psum = make_float4(0.f, 0.f, 0.f, 0.f);
    float4 psq  = make_float4(0.f, 0.f, 0.f, 0.f);

    for (int node = blockIdx.x * gpb + grp; node < n; node += gridDim.x * gpb) {
        const int* row = &g_csr[node * CAP];
        int cnt = g_cur[node];
        float4 a0 = base[node * 8 + sub];   // self-loop term
        float4 a1 = make_float4(0.f, 0.f, 0.f, 0.f);
        int j = 0;
        for (; j + 8 <= cnt; j += 8) {
            int i0 = __ldg(row + j);
            int i1 = __ldg(row + j + 1);
            int i2 = __ldg(row + j + 2);
            int i3 = __ldg(row + j + 3);
            int i4 = __ldg(row + j + 4);
            int i5 = __ldg(row + j + 5);
            int i6 = __ldg(row + j + 6);
            int i7 = __ldg(row + j + 7);
            float4 v0 = base[i0 * 8 + sub];
            float4 v1 = base[i1 * 8 + sub];
            float4 v2 = base[i2 * 8 + sub];
            float4 v3 = base[i3 * 8 + sub];
            float4 v4 = base[i4 * 8 + sub];
            float4 v5 = base[i5 * 8 + sub];
            float4 v6 = base[i6 * 8 + sub];
            float4 v7 = base[i7 * 8 + sub];
            a0.x += (v0.x + v1.x) + (v2.x + v3.x);
            a0.y += (v0.y + v1.y) + (v2.y + v3.y);
            a0.z += (v0.z + v1.z) + (v2.z + v3.z);
            a0.w += (v0.w + v1.w) + (v2.w + v3.w);
            a1.x += (v4.x + v5.x) + (v6.x + v7.x);
            a1.y += (v4.y + v5.y) + (v6.y + v7.y);
            a1.z += (v4.z + v5.z) + (v6.z + v7.z);
            a1.w += (v4.w + v5.w) + (v6.w + v7.w);
        }
        for (; j + 2 <= cnt; j += 2) {
            int i0 = __ldg(row + j);
            int i1 = __ldg(row + j + 1);
            float4 v0 = base[i0 * 8 + sub];
            float4 v1 = base[i1 * 8 + sub];
            a0.x += v0.x; a0.y += v0.y; a0.z += v0.z; a0.w += v0.w;
            a1.x += v1.x; a1.y += v1.y; a1.z += v1.z; a1.w += v1.w;
        }
        if (j < cnt) {
            int i0 = __ldg(row + j);
            float4 v0 = base[i0 * 8 + sub];
            a0.x += v0.x; a0.y += v0.y; a0.z += v0.z; a0.w += v0.w;
        }
        float dinv = g_dinv[node];
        float4 v;
        v.x = fmaf(a0.x + a1.x, dinv, bf.x);
        v.y = fmaf(a0.y + a1.y, dinv, bf.y);
        v.z = fmaf(a0.z + a1.z, dinv, bf.z);
        v.w = fmaf(a0.w + a1.w, dinv, bf.w);
        preb[node * 8 + sub] = v;
        psum.x += v.x; psum.y += v.y; psum.z += v.z; psum.w += v.w;
        psq.x = fmaf(v.x, v.x, psq.x); psq.y = fmaf(v.y, v.y, psq.y);
        psq.z = fmaf(v.z, v.z, psq.z); psq.w = fmaf(v.w, v.w, psq.w);
    }

    int f = sub * 4;
    atomicAdd(&ssum[f + 0], psum.x); atomicAdd(&ssum[f + 1], psum.y);
    atomicAdd(&ssum[f + 2], psum.z); atomicAdd(&ssum[f + 3], psum.w);
    atomicAdd(&ssq[f + 0], psq.x);   atomicAdd(&ssq[f + 1], psq.y);
    atomicAdd(&ssq[f + 2], psq.z);   atomicAdd(&ssq[f + 3], psq.w);
    __syncthreads();
    if (threadIdx.x < D) {
        atomicAdd(&g_stats[off + threadIdx.x],      ssum[threadIdx.x]);
        atomicAdd(&g_stats[off + 32 + threadIdx.x], ssq[threadIdx.x]);
    }
}

// bn+relu of layer-1 (folded affine), h@W2 (register W column), scale by dinv
__global__ void k_node2(const float* __restrict__ W, const float* __restrict__ g,
                        const float* __restrict__ be, int off, float inv_n, int n) {
    int lane = threadIdx.x & 31;
    int warp = threadIdx.x >> 5;
    int wpb  = blockDim.x >> 5;
    float wcol[D];
#pragma unroll
    for (int k = 0; k < D; k++) wcol[k] = (lane < D) ? W[k * D + lane] : 0.f;

    float A = 0.f, B = 0.f;
    if (lane < D) {
        float mu  = g_stats[off + lane] * inv_n;
        float var = g_stats[off + 32 + lane] * inv_n - mu * mu;
        float rs  = rsqrtf(var + EPS);
        A = rs * g[lane];
        B = be[lane] - mu * A;
    }

    for (int node = blockIdx.x * wpb + warp; node < n; node += gridDim.x * wpb) {
        float pre = g_pre[node * STRIDE + lane];
        float h = fmaxf(fmaf(pre, A, B), 0.f);   // lanes>=D: A=B=0 -> 0
        float acc = 0.f;
#pragma unroll
        for (int k = 0; k < D; k++)
            acc = fmaf(__shfl_sync(0xffffffffu, h, k), wcol[k], acc);
        float dinv = g_dinv[node];
        g_hw[node * STRIDE + lane] = (lane < D) ? acc * dinv : 0.f;
    }
}

// bn+relu of layer-2 (folded affine), MLP head (25->12 relu ->1), sigmoid;
// also resets g_cur to 0 for the next launch.
__global__ void k_final(const float* __restrict__ g, const float* __restrict__ be,
                        const float* __restrict__ Wm1, const float* __restrict__ bm1,
                        const float* __restrict__ Wm2, const float* __restrict__ bm2,
                        float* __restrict__ out, int off, float inv_n, int n) {
    int lane = threadIdx.x & 31;
    int warp = threadIdx.x >> 5;
    int wpb  = blockDim.x >> 5;
    float wcol[D];
#pragma unroll
    for (int k = 0; k < D; k++) wcol[k] = (lane < 12) ? Wm1[k * 12 + lane] : 0.f;
    float wm2 = (lane < 12) ? Wm2[lane] : 0.f;
    float bmv = (lane < 12) ? bm1[lane] : 0.f;
    float bm2v = bm2[0];

    float A = 0.f, B = 0.f;
    if (lane < D) {
        float mu  = g_stats[off + lane] * inv_n;
        float var = g_stats[off + 32 + lane] * inv_n - mu * mu;
        float rs  = rsqrtf(var + EPS);
        A = rs * g[lane];
        B = be[lane] - mu * A;
    }

    for (int node = blockIdx.x * wpb + warp; node < n; node += gridDim.x * wpb) {
        float pre = g_pre[node * STRIDE + lane];
        float h = fmaxf(fmaf(pre, A, B), 0.f);
        float m = 0.f;
#pragma unroll
        for (int k = 0; k < D; k++)
            m = fmaf(__shfl_sync(0xffffffffu, h, k), wcol[k], m);
        float t = 0.f;
        if (lane < 12) {
            m = fmaxf(m + bmv, 0.f);
            t = m * wm2;
        }
#pragma unroll
        for (int o = 16; o > 0; o >>= 1) t += __shfl_down_sync(0xffffffffu, t, o);
        if (lane == 0) {
            float z = t + bm2v;
            out[node] = 1.f / (1.f + __expf(-z));
            g_cur[node] = 0;   // restore invariant for next launch
        }
    }
}

// ---------------- launch -----------------------------------------------------

extern "C" void kernel_launch(void* const* d_in, const int* in_sizes, int n_in,
                              void* d_out, int out_size) {
    const int*   x   = (const int*)d_in[0];
    const int*   ei  = (const int*)d_in[1];
    const float* emb = (const float*)d_in[2];
    const float* W1  = (const float*)d_in[3];
    const float* b1  = (const float*)d_in[4];
    const float* g1  = (const float*)d_in[5];
    const float* be1 = (const float*)d_in[6];
    const float* W2  = (const float*)d_in[7];
    const float* b2  = (const float*)d_in[8];
    const float* g2  = (const float*)d_in[9];
    const float* be2 = (const float*)d_in[10];
    const float* Wm1 = (const float*)d_in[11];
    const float* bm1 = (const float*)d_in[12];
    const float* Wm2 = (const float*)d_in[13];
    const float* bm2 = (const float*)d_in[14];
    float* out = (float*)d_out;

    int n = in_sizes[0];
    int E = in_sizes[1] / 2;
    float inv_n = 1.f / (float)n;

    int eb4 = ((E + 3) / 4 + 255) / 256;   // 4 edges/thread

    k_fill<<<eb4, 256>>>(ei, E);

    k_node1<<<1184, 256>>>(x, emb, W1, n);
    k_agg<<<1184, 256>>>(b1, 0, n);

    k_node2<<<1184, 256>>>(W2, g1, be1, 0, inv_n, n);
    k_agg<<<1184, 256>>>(b2, 128, n);

    k_final<<<1184, 256>>>(g2, be2, Wm1, bm1, Wm2, bm2, out, 128, inv_n, n);
}

// round 13
// speedup vs baseline: 1.3332x; 1.0215x over previous
#include <cuda_runtime.h>
#include <math.h>

#define N_MAX   200000
#define E_MAX   3200000
#define D       25
#define STRIDE  32
#define CAP     64         // fixed CSR capacity per node (Poisson(16): P(deg>=64) ~ 1e-17)
#define EPS     1e-5f

// ---------------- scratch (device globals; no allocation allowed) -----------
__device__ __align__(16) float g_hw[N_MAX * STRIDE];   // dinv-scaled h@W messages
__device__ __align__(16) float g_pre[N_MAX * STRIDE];  // pre-batchnorm activations
__device__ __align__(16) int   g_csr[N_MAX * CAP];     // fixed-capacity per-dst neighbor lists (51MB)
__device__ int   g_cur[N_MAX];       // fill cursor == in-degree; reset to 0 by k_final each launch
__device__ float g_dinv[N_MAX];
__device__ float g_stats[256];       // L1 @0: [0:25)=sum [32:57)=sumsq ; L2 @128; reset by k_fill

// ---------------- kernels ---------------------------------------------------

// one-pass CSR build: 8 edges per thread; block 0 also re-zeros g_stats
__global__ void k_fill(const int* __restrict__ ei, int E) {
    if (blockIdx.x == 0 && threadIdx.x < 256) g_stats[threadIdx.x] = 0.f;
    int t = blockIdx.x * blockDim.x + threadIdx.x;
    int e = t * 8;
    if (e + 7 < E) {
        int4 s0 = *(const int4*)(ei + e);
        int4 s1 = *(const int4*)(ei + e + 4);
        int4 d0 = *(const int4*)(ei + E + e);
        int4 d1 = *(const int4*)(ei + E + e + 4);
        int p0 = atomicAdd(&g_cur[d0.x], 1);
        int p1 = atomicAdd(&g_cur[d0.y], 1);
        int p2 = atomicAdd(&g_cur[d0.z], 1);
        int p3 = atomicAdd(&g_cur[d0.w], 1);
        int p4 = atomicAdd(&g_cur[d1.x], 1);
        int p5 = atomicAdd(&g_cur[d1.y], 1);
        int p6 = atomicAdd(&g_cur[d1.z], 1);
        int p7 = atomicAdd(&g_cur[d1.w], 1);
        g_csr[d0.x * CAP + p0] = s0.x;
        g_csr[d0.y * CAP + p1] = s0.y;
        g_csr[d0.z * CAP + p2] = s0.z;
        g_csr[d0.w * CAP + p3] = s0.w;
        g_csr[d1.x * CAP + p4] = s1.x;
        g_csr[d1.y * CAP + p5] = s1.y;
        g_csr[d1.z * CAP + p6] = s1.z;
        g_csr[d1.w * CAP + p7] = s1.w;
    } else {
        for (; e < E; e++) {
            int sv = ei[e];
            int dv = ei[E + e];
            int p = atomicAdd(&g_cur[dv], 1);
            g_csr[dv * CAP + p] = sv;
        }
    }
}

// gather emb[x], h@W1 (register W column), scale by dinv — 2 nodes per warp iter
__global__ void k_node1(const int* __restrict__ x, const float* __restrict__ emb,
                        const float* __restrict__ W, int n) {
    int lane = threadIdx.x & 31;
    int warp = threadIdx.x >> 5;
    int wpb  = blockDim.x >> 5;
    float wcol[D];
#pragma unroll
    for (int k = 0; k < D; k++) wcol[k] = (lane < D) ? W[k * D + lane] : 0.f;

    int stridePairs = gridDim.x * wpb;
    for (int pair = blockIdx.x * wpb + warp; 2 * pair < n; pair += stridePairs) {
        int n0 = 2 * pair;
        int n1 = n0 + 1;
        bool has1 = (n1 < n);

        float dinv0 = rsqrtf((float)(g_cur[n0] + 1));
        float dinv1 = has1 ? rsqrtf((float)(g_cur[n1] + 1)) : 0.f;
        if (lane == 0) {
            g_dinv[n0] = dinv0;
            if (has1) g_dinv[n1] = dinv1;
        }
        int x0 = x[n0];
        int x1 = has1 ? x[n1] : x[n0];
        float h0 = (lane < D) ? __ldg(&emb[x0 * D + lane]) : 0.f;
        float h1 = (lane < D) ? __ldg(&emb[x1 * D + lane]) : 0.f;

        float a0 = 0.f, a1 = 0.f;
#pragma unroll
        for (int k = 0; k < D; k++) {
            float w = wcol[k];
            a0 = fmaf(__shfl_sync(0xffffffffu, h0, k), w, a0);
            a1 = fmaf(__shfl_sync(0xffffffffu, h1, k), w, a1);
        }
        g_hw[n0 * STRIDE + lane] = (lane < D) ? a0 * dinv0 : 0.f;
        if (has1) g_hw[n1 * STRIDE + lane] = (lane < D) ? a1 * dinv1 : 0.f;
    }
}

// gather aggregation: 8 threads per node, float4 per thread, unroll 8,
// int4 index loads, launch_bounds for occupancy.
__global__ void __launch_bounds__(256, 6) k_agg(const float* __restrict__ b, int off, int n) {
    __shared__ float sb[32];
    __shared__ float ssum[32], ssq[32];
    if (threadIdx.x < 32) {
        sb[threadIdx.x]   = (threadIdx.x < D) ? b[threadIdx.x] : 0.f;
        ssum[threadIdx.x] = 0.f;
        ssq[threadIdx.x]  = 0.f;
    }
    __syncthreads();

    int sub = threadIdx.x & 7;        // float4 slot within row
    int grp = threadIdx.x >> 3;       // node slot within block
    int gpb = blockDim.x >> 3;
    const float4* base = (const float4*)g_hw;
    float4* preb = (float4*)g_pre;
    float4 bf = ((const float4*)sb)[sub];
    float4 psum = make_float4(0.f, 0.f, 0.f, 0.f);
    float4 psq  = make_float4(0.f, 0.f, 0.f, 0.f);

    for (int node = blockIdx.x * gpb + grp; node < n; node += gridDim.x * gpb) {
        const int4* r4 = (const int4*)&g_csr[node * CAP];
        int cnt = g_cur[node];
        float4 a0 = base[node * 8 + sub];   // self-loop term
        float4 a1 = make_float4(0.f, 0.f, 0.f, 0.f);
        int j = 0;
        for (; j + 8 <= cnt; j += 8) {
            int4 iA = __ldg(&r4[j >> 2]);
            int4 iB = __ldg(&r4[(j >> 2) + 1]);
            float4 v0 = base[iA.x * 8 + sub];
            float4 v1 = base[iA.y * 8 + sub];
            float4 v2 = base[iA.z * 8 + sub];
            float4 v3 = base[iA.w * 8 + sub];
            float4 v4 = base[iB.x * 8 + sub];
            float4 v5 = base[iB.y * 8 + sub];
            float4 v6 = base[iB.z * 8 + sub];
            float4 v7 = base[iB.w * 8 + sub];
            a0.x += (v0.x + v1.x) + (v2.x + v3.x);
            a0.y += (v0.y + v1.y) + (v2.y + v3.y);
            a0.z += (v0.z + v1.z) + (v2.z + v3.z);
            a0.w += (v0.w + v1.w) + (v2.w + v3.w);
            a1.x += (v4.x + v5.x) + (v6.x + v7.x);
            a1.y += (v4.y + v5.y) + (v6.y + v7.y);
            a1.z += (v4.z + v5.z) + (v6.z + v7.z);
            a1.w += (v4.w + v5.w) + (v6.w + v7.w);
        }
        if (j + 4 <= cnt) {
            int4 iA = __ldg(&r4[j >> 2]);
            float4 v0 = base[iA.x * 8 + sub];
            float4 v1 = base[iA.y * 8 + sub];
            float4 v2 = base[iA.z * 8 + sub];
            float4 v3 = base[iA.w * 8 + sub];
            a0.x += (v0.x + v1.x) + (v2.x + v3.x);
            a0.y += (v0.y + v1.y) + (v2.y + v3.y);
            a0.z += (v0.z + v1.z) + (v2.z + v3.z);
            a0.w += (v0.w + v1.w) + (v2.w + v3.w);
            j += 4;
        }
        const int* row = (const int*)r4;
        for (; j < cnt; j++) {
            int i0 = __ldg(row + j);
            float4 v0 = base[i0 * 8 + sub];
            a1.x += v0.x; a1.y += v0.y; a1.z += v0.z; a1.w += v0.w;
        }
        float dinv = g_dinv[node];
        float4 v;
        v.x = fmaf(a0.x + a1.x, dinv, bf.x);
        v.y = fmaf(a0.y + a1.y, dinv, bf.y);
        v.z = fmaf(a0.z + a1.z, dinv, bf.z);
        v.w = fmaf(a0.w + a1.w, dinv, bf.w);
        preb[node * 8 + sub] = v;
        psum.x += v.x; psum.y += v.y; psum.z += v.z; psum.w += v.w;
        psq.x = fmaf(v.x, v.x, psq.x); psq.y = fmaf(v.y, v.y, psq.y);
        psq.z = fmaf(v.z, v.z, psq.z); psq.w = fmaf(v.w, v.w, psq.w);
    }

    int f = sub * 4;
    atomicAdd(&ssum[f + 0], psum.x); atomicAdd(&ssum[f + 1], psum.y);
    atomicAdd(&ssum[f + 2], psum.z); atomicAdd(&ssum[f + 3], psum.w);
    atomicAdd(&ssq[f + 0], psq.x);   atomicAdd(&ssq[f + 1], psq.y);
    atomicAdd(&ssq[f + 2], psq.z);   atomicAdd(&ssq[f + 3], psq.w);
    __syncthreads();
    if (threadIdx.x < D) {
        atomicAdd(&g_stats[off + threadIdx.x],      ssum[threadIdx.x]);
        atomicAdd(&g_stats[off + 32 + threadIdx.x], ssq[threadIdx.x]);
    }
}

// bn+relu (folded affine), h@W2 (register W column), scale by dinv — 2 nodes per iter
__global__ void k_node2(const float* __restrict__ W, const float* __restrict__ g,
                        const float* __restrict__ be, int off, float inv_n, int n) {
    int lane = threadIdx.x & 31;
    int warp = threadIdx.x >> 5;
    int wpb  = blockDim.x >> 5;
    float wcol[D];
#pragma unroll
    for (int k = 0; k < D; k++) wcol[k] = (lane < D) ? W[k * D + lane] : 0.f;

    float A = 0.f, B = 0.f;
    if (lane < D) {
        float mu  = g_stats[off + lane] * inv_n;
        float var = g_stats[off + 32 + lane] * inv_n - mu * mu;
        float rs  = rsqrtf(var + EPS);
        A = rs * g[lane];
        B = be[lane] - mu * A;
    }

    int stridePairs = gridDim.x * wpb;
    for (int pair = blockIdx.x * wpb + warp; 2 * pair < n; pair += stridePairs) {
        int n0 = 2 * pair;
        int n1 = n0 + 1;
        bool has1 = (n1 < n);

        float p0 = g_pre[n0 * STRIDE + lane];
        float p1 = has1 ? g_pre[n1 * STRIDE + lane] : 0.f;
        float h0 = fmaxf(fmaf(p0, A, B), 0.f);
        float h1 = fmaxf(fmaf(p1, A, B), 0.f);

        float a0 = 0.f, a1 = 0.f;
#pragma unroll
        for (int k = 0; k < D; k++) {
            float w = wcol[k];
            a0 = fmaf(__shfl_sync(0xffffffffu, h0, k), w, a0);
            a1 = fmaf(__shfl_sync(0xffffffffu, h1, k), w, a1);
        }
        float dinv0 = g_dinv[n0];
        g_hw[n0 * STRIDE + lane] = (lane < D) ? a0 * dinv0 : 0.f;
        if (has1) {
            float dinv1 = g_dinv[n1];
            g_hw[n1 * STRIDE + lane] = (lane < D) ? a1 * dinv1 : 0.f;
        }
    }
}

// bn+relu (folded affine), MLP head (25->12 relu ->1), sigmoid — 2 nodes per iter;
// also resets g_cur to 0 for the next launch.
__global__ void k_final(const float* __restrict__ g, const float* __restrict__ be,
                        const float* __restrict__ Wm1, const float* __restrict__ bm1,
                        const float* __restrict__ Wm2, const float* __restrict__ bm2,
                        float* __restrict__ out, int off, float inv_n, int n) {
    int lane = threadIdx.x & 31;
    int warp = threadIdx.x >> 5;
    int wpb  = blockDim.x >> 5;
    float wcol[D];
#pragma unroll
    for (int k = 0; k < D; k++) wcol[k] = (lane < 12) ? Wm1[k * 12 + lane] : 0.f;
    float wm2 = (lane < 12) ? Wm2[lane] : 0.f;
    float bmv = (lane < 12) ? bm1[lane] : 0.f;
    float bm2v = bm2[0];

    float A = 0.f, B = 0.f;
    if (lane < D) {
        float mu  = g_stats[off + lane] * inv_n;
        float var = g_stats[off + 32 + lane] * inv_n - mu * mu;
        float rs  = rsqrtf(var + EPS);
        A = rs * g[lane];
        B = be[lane] - mu * A;
    }

    int stridePairs = gridDim.x * wpb;
    for (int pair = blockIdx.x * wpb + warp; 2 * pair < n; pair += stridePairs) {
        int n0 = 2 * pair;
        int n1 = n0 + 1;
        bool has1 = (n1 < n);

        float p0 = g_pre[n0 * STRIDE + lane];
        float p1 = has1 ? g_pre[n1 * STRIDE + lane] : 0.f;
        float h0 = fmaxf(fmaf(p0, A, B), 0.f);
        float h1 = fmaxf(fmaf(p1, A, B), 0.f);

        float m0 = 0.f, m1 = 0.f;
#pragma unroll
        for (int k = 0; k < D; k++) {
            float w = wcol[k];
            m0 = fmaf(__shfl_sync(0xffffffffu, h0, k), w, m0);
            m1 = fmaf(__shfl_sync(0xffffffffu, h1, k), w, m1);
        }
        float t0 = 0.f, t1 = 0.f;
        if (lane < 12) {
            t0 = fmaxf(m0 + bmv, 0.f) * wm2;
            t1 = fmaxf(m1 + bmv, 0.f) * wm2;
        }
#pragma unroll
        for (int o = 16; o > 0; o >>= 1) {
            t0 += __shfl_down_sync(0xffffffffu, t0, o);
            t1 += __shfl_down_sync(0xffffffffu, t1, o);
        }
        if (lane == 0) {
            out[n0] = 1.f / (1.f + __expf(-(t0 + bm2v)));
            g_cur[n0] = 0;
            if (has1) {
                out[n1] = 1.f / (1.f + __expf(-(t1 + bm2v)));
                g_cur[n1] = 0;
            }
        }
    }
}

// ---------------- launch -----------------------------------------------------

extern "C" void kernel_launch(void* const* d_in, const int* in_sizes, int n_in,
                              void* d_out, int out_size) {
    const int*   x   = (const int*)d_in[0];
    const int*   ei  = (const int*)d_in[1];
    const float* emb = (const float*)d_in[2];
    const float* W1  = (const float*)d_in[3];
    const float* b1  = (const float*)d_in[4];
    const float* g1  = (const float*)d_in[5];
    const float* be1 = (const float*)d_in[6];
    const float* W2  = (const float*)d_in[7];
    const float* b2  = (const float*)d_in[8];
    const float* g2  = (const float*)d_in[9];
    const float* be2 = (const float*)d_in[10];
    const float* Wm1 = (const float*)d_in[11];
    const float* bm1 = (const float*)d_in[12];
    const float* Wm2 = (const float*)d_in[13];
    const float* bm2 = (const float*)d_in[14];
    float* out = (float*)d_out;

    int n = in_sizes[0];
    int E = in_sizes[1] / 2;
    float inv_n = 1.f / (float)n;

    int eb8 = ((E + 7) / 8 + 255) / 256;   // 8 edges/thread

    k_fill<<<eb8, 256>>>(ei, E);

    k_node1<<<1184, 256>>>(x, emb, W1, n);
    k_agg<<<1184, 256>>>(b1, 0, n);

    k_node2<<<1184, 256>>>(W2, g1, be1, 0, inv_n, n);
    k_agg<<<1184, 256>>>(b2, 128, n);

    k_final<<<1184, 256>>>(g2, be2, Wm1, bm1, Wm2, bm2, out, 128, inv_n, n);
}

// round 14
// speedup vs baseline: 1.3700x; 1.0276x over previous
#include <cuda_runtime.h>
#include <math.h>

#define N_MAX   200000
#define E_MAX   3200000
#define D       25
#define STRIDE  32
#define CAP     64         // fixed CSR capacity per node (Poisson(16): P(deg>=64) ~ 1e-17)
#define EPS     1e-5f
#define NB1     1184       // node-work virtual blocks in fused kernel

// ---------------- scratch (device globals; no allocation allowed) -----------
__device__ __align__(16) float g_hw[N_MAX * STRIDE];   // h@W messages (unscaled, then dinv-scaled)
__device__ __align__(16) float g_pre[N_MAX * STRIDE];  // pre-batchnorm activations
__device__ __align__(16) int   g_csr[N_MAX * CAP];     // fixed-capacity per-dst neighbor lists (51MB)
__device__ int   g_cur[N_MAX];       // fill cursor == in-degree; reset to 0 by k_final each launch
__device__ float g_dinv[N_MAX];
__device__ float g_stats[256];       // L1 @0: [0:25)=sum [32:57)=sumsq ; L2 @128

// ---------------- kernels ---------------------------------------------------

// fused: even-parity blocks build CSR (8 edges/thread), odd-parity blocks compute
// h@W1 unscaled (independent of fill). Interleaving co-schedules latency-bound
// atomics with issue-bound matmul on the same SMs.
__global__ void k_fill_node1(const int* __restrict__ ei, int E,
                             const int* __restrict__ x, const float* __restrict__ emb,
                             const float* __restrict__ W, int n, int FB) {
    int bid = blockIdx.x;
    int role, id;
    int m2 = 2 * NB1;            // FB > NB1 always here
    if (bid < m2) { role = bid & 1; id = bid >> 1; }
    else          { role = 0;       id = bid - m2 + NB1; }

    if (role == 0) {
        // ---- fill ----
        if (id == 0 && threadIdx.x < 256) g_stats[threadIdx.x] = 0.f;
        int t = id * blockDim.x + threadIdx.x;
        int e = t * 8;
        if (e + 7 < E) {
            int4 s0 = *(const int4*)(ei + e);
            int4 s1 = *(const int4*)(ei + e + 4);
            int4 d0 = *(const int4*)(ei + E + e);
            int4 d1 = *(const int4*)(ei + E + e + 4);
            int p0 = atomicAdd(&g_cur[d0.x], 1);
            int p1 = atomicAdd(&g_cur[d0.y], 1);
            int p2 = atomicAdd(&g_cur[d0.z], 1);
            int p3 = atomicAdd(&g_cur[d0.w], 1);
            int p4 = atomicAdd(&g_cur[d1.x], 1);
            int p5 = atomicAdd(&g_cur[d1.y], 1);
            int p6 = atomicAdd(&g_cur[d1.z], 1);
            int p7 = atomicAdd(&g_cur[d1.w], 1);
            g_csr[d0.x * CAP + p0] = s0.x;
            g_csr[d0.y * CAP + p1] = s0.y;
            g_csr[d0.z * CAP + p2] = s0.z;
            g_csr[d0.w * CAP + p3] = s0.w;
            g_csr[d1.x * CAP + p4] = s1.x;
            g_csr[d1.y * CAP + p5] = s1.y;
            g_csr[d1.z * CAP + p6] = s1.z;
            g_csr[d1.w * CAP + p7] = s1.w;
        } else {
            for (; e < E; e++) {
                int sv = ei[e];
                int dv = ei[E + e];
                int p = atomicAdd(&g_cur[dv], 1);
                g_csr[dv * CAP + p] = sv;
            }
        }
    } else {
        // ---- node1: emb gather + h@W1 (register W column), UNSCALED, 2 nodes/iter ----
        int lane = threadIdx.x & 31;
        int warp = threadIdx.x >> 5;
        int wpb  = blockDim.x >> 5;
        float wcol[D];
#pragma unroll
        for (int k = 0; k < D; k++) wcol[k] = (lane < D) ? W[k * D + lane] : 0.f;

        int stridePairs = NB1 * wpb;
        for (int pair = id * wpb + warp; 2 * pair < n; pair += stridePairs) {
            int n0 = 2 * pair;
            int n1 = n0 + 1;
            bool has1 = (n1 < n);
            int x0 = x[n0];
            int x1 = has1 ? x[n1] : x[n0];
            float h0 = (lane < D) ? __ldg(&emb[x0 * D + lane]) : 0.f;
            float h1 = (lane < D) ? __ldg(&emb[x1 * D + lane]) : 0.f;
            float a0 = 0.f, a1 = 0.f;
#pragma unroll
            for (int k = 0; k < D; k++) {
                float w = wcol[k];
                a0 = fmaf(__shfl_sync(0xffffffffu, h0, k), w, a0);
                a1 = fmaf(__shfl_sync(0xffffffffu, h1, k), w, a1);
            }
            g_hw[n0 * STRIDE + lane] = (lane < D) ? a0 : 0.f;
            if (has1) g_hw[n1 * STRIDE + lane] = (lane < D) ? a1 : 0.f;
        }
    }
}

// scale messages by dinv = rsqrt(deg+1); write g_dinv. Thread per float4 slot.
__global__ void k_scale(int n) {
    int gid = blockIdx.x * blockDim.x + threadIdx.x;
    if (gid >= n * 8) return;
    int node = gid >> 3;
    int sub  = gid & 7;
    float dinv = rsqrtf((float)(g_cur[node] + 1));
    if (sub == 0) g_dinv[node] = dinv;
    float4* p = (float4*)g_hw + gid;
    float4 v = *p;
    v.x *= dinv; v.y *= dinv; v.z *= dinv; v.w *= dinv;
    *p = v;
}

// gather aggregation: 8 threads per node, float4 per thread, unroll 8, int4 index loads
__global__ void __launch_bounds__(256, 6) k_agg(const float* __restrict__ b, int off, int n) {
    __shared__ float sb[32];
    __shared__ float ssum[32], ssq[32];
    if (threadIdx.x < 32) {
        sb[threadIdx.x]   = (threadIdx.x < D) ? b[threadIdx.x] : 0.f;
        ssum[threadIdx.x] = 0.f;
        ssq[threadIdx.x]  = 0.f;
    }
    __syncthreads();

    int sub = threadIdx.x & 7;
    int grp = threadIdx.x >> 3;
    int gpb = blockDim.x >> 3;
    const float4* base = (const float4*)g_hw;
    float4* preb = (float4*)g_pre;
    float4 bf = ((const float4*)sb)[sub];
    float4 psum = make_float4(0.f, 0.f, 0.f, 0.f);
    float4 psq  = make_float4(0.f, 0.f, 0.f, 0.f);

    for (int node = blockIdx.x * gpb + grp; node < n; node += gridDim.x * gpb) {
        const int4* r4 = (const int4*)&g_csr[node * CAP];
        int cnt = g_cur[node];
        float4 a0 = base[node * 8 + sub];   // self-loop term
        float4 a1 = make_float4(0.f, 0.f, 0.f, 0.f);
        int j = 0;
        for (; j + 8 <= cnt; j += 8) {
            int4 iA = __ldg(&r4[j >> 2]);
            int4 iB = __ldg(&r4[(j >> 2) + 1]);
            float4 v0 = base[iA.x * 8 + sub];
            float4 v1 = base[iA.y * 8 + sub];
            float4 v2 = base[iA.z * 8 + sub];
            float4 v3 = base[iA.w * 8 + sub];
            float4 v4 = base[iB.x * 8 + sub];
            float4 v5 = base[iB.y * 8 + sub];
            float4 v6 = base[iB.z * 8 + sub];
            float4 v7 = base[iB.w * 8 + sub];
            a0.x += (v0.x + v1.x) + (v2.x + v3.x);
            a0.y += (v0.y + v1.y) + (v2.y + v3.y);
            a0.z += (v0.z + v1.z) + (v2.z + v3.z);
            a0.w += (v0.w + v1.w) + (v2.w + v3.w);
            a1.x += (v4.x + v5.x) + (v6.x + v7.x);
            a1.y += (v4.y + v5.y) + (v6.y + v7.y);
            a1.z += (v4.z + v5.z) + (v6.z + v7.z);
            a1.w += (v4.w + v5.w) + (v6.w + v7.w);
        }
        if (j + 4 <= cnt) {
            int4 iA = __ldg(&r4[j >> 2]);
            float4 v0 = base[iA.x * 8 + sub];
            float4 v1 = base[iA.y * 8 + sub];
            float4 v2 = base[iA.z * 8 + sub];
            float4 v3 = base[iA.w * 8 + sub];
            a0.x += (v0.x + v1.x) + (v2.x + v3.x);
            a0.y += (v0.y + v1.y) + (v2.y + v3.y);
            a0.z += (v0.z + v1.z) + (v2.z + v3.z);
            a0.w += (v0.w + v1.w) + (v2.w + v3.w);
            j += 4;
        }
        const int* row = (const int*)r4;
        for (; j < cnt; j++) {
            int i0 = __ldg(row + j);
            float4 v0 = base[i0 * 8 + sub];
            a1.x += v0.x; a1.y += v0.y; a1.z += v0.z; a1.w += v0.w;
        }
        float dinv = g_dinv[node];
        float4 v;
        v.x = fmaf(a0.x + a1.x, dinv, bf.x);
        v.y = fmaf(a0.y + a1.y, dinv, bf.y);
        v.z = fmaf(a0.z + a1.z, dinv, bf.z);
        v.w = fmaf(a0.w + a1.w, dinv, bf.w);
        preb[node * 8 + sub] = v;
        psum.x += v.x; psum.y += v.y; psum.z += v.z; psum.w += v.w;
        psq.x = fmaf(v.x, v.x, psq.x); psq.y = fmaf(v.y, v.y, psq.y);
        psq.z = fmaf(v.z, v.z, psq.z); psq.w = fmaf(v.w, v.w, psq.w);
    }

    int f = sub * 4;
    atomicAdd(&ssum[f + 0], psum.x); atomicAdd(&ssum[f + 1], psum.y);
    atomicAdd(&ssum[f + 2], psum.z); atomicAdd(&ssum[f + 3], psum.w);
    atomicAdd(&ssq[f + 0], psq.x);   atomicAdd(&ssq[f + 1], psq.y);
    atomicAdd(&ssq[f + 2], psq.z);   atomicAdd(&ssq[f + 3], psq.w);
    __syncthreads();
    if (threadIdx.x < D) {
        atomicAdd(&g_stats[off + threadIdx.x],      ssum[threadIdx.x]);
        atomicAdd(&g_stats[off + 32 + threadIdx.x], ssq[threadIdx.x]);
    }
}

// bn+relu (folded affine), h@W2 (register W column), scale by dinv — 2 nodes/iter
__global__ void k_node2(const float* __restrict__ W, const float* __restrict__ g,
                        const float* __restrict__ be, int off, float inv_n, int n) {
    int lane = threadIdx.x & 31;
    int warp = threadIdx.x >> 5;
    int wpb  = blockDim.x >> 5;
    float wcol[D];
#pragma unroll
    for (int k = 0; k < D; k++) wcol[k] = (lane < D) ? W[k * D + lane] : 0.f;

    float A = 0.f, B = 0.f;
    if (lane < D) {
        float mu  = g_stats[off + lane] * inv_n;
        float var = g_stats[off + 32 + lane] * inv_n - mu * mu;
        float rs  = rsqrtf(var + EPS);
        A = rs * g[lane];
        B = be[lane] - mu * A;
    }

    int stridePairs = gridDim.x * wpb;
    for (int pair = blockIdx.x * wpb + warp; 2 * pair < n; pair += stridePairs) {
        int n0 = 2 * pair;
        int n1 = n0 + 1;
        bool has1 = (n1 < n);
        float p0 = g_pre[n0 * STRIDE + lane];
        float p1 = has1 ? g_pre[n1 * STRIDE + lane] : 0.f;
        float h0 = fmaxf(fmaf(p0, A, B), 0.f);
        float h1 = fmaxf(fmaf(p1, A, B), 0.f);
        float a0 = 0.f, a1 = 0.f;
#pragma unroll
        for (int k = 0; k < D; k++) {
            float w = wcol[k];
            a0 = fmaf(__shfl_sync(0xffffffffu, h0, k), w, a0);
            a1 = fmaf(__shfl_sync(0xffffffffu, h1, k), w, a1);
        }
        float dinv0 = g_dinv[n0];
        g_hw[n0 * STRIDE + lane] = (lane < D) ? a0 * dinv0 : 0.f;
        if (has1) {
            float dinv1 = g_dinv[n1];
            g_hw[n1 * STRIDE + lane] = (lane < D) ? a1 * dinv1 : 0.f;
        }
    }
}

// bn+relu (folded affine), MLP head, sigmoid — 2 nodes/iter; resets g_cur.
__global__ void k_final(const float* __restrict__ g, const float* __restrict__ be,
                        const float* __restrict__ Wm1, const float* __restrict__ bm1,
                        const float* __restrict__ Wm2, const float* __restrict__ bm2,
                        float* __restrict__ out, int off, float inv_n, int n) {
    int lane = threadIdx.x & 31;
    int warp = threadIdx.x >> 5;
    int wpb  = blockDim.x >> 5;
    float wcol[D];
#pragma unroll
    for (int k = 0; k < D; k++) wcol[k] = (lane < 12) ? Wm1[k * 12 + lane] : 0.f;
    float wm2 = (lane < 12) ? Wm2[lane] : 0.f;
    float bmv = (lane < 12) ? bm1[lane] : 0.f;
    float bm2v = bm2[0];

    float A = 0.f, B = 0.f;
    if (lane < D) {
        float mu  = g_stats[off + lane] * inv_n;
        float var = g_stats[off + 32 + lane] * inv_n - mu * mu;
        float rs  = rsqrtf(var + EPS);
        A = rs * g[lane];
        B = be[lane] - mu * A;
    }

    int stridePairs = gridDim.x * wpb;
    for (int pair = blockIdx.x * wpb + warp; 2 * pair < n; pair += stridePairs) {
        int n0 = 2 * pair;
        int n1 = n0 + 1;
        bool has1 = (n1 < n);
        float p0 = g_pre[n0 * STRIDE + lane];
        float p1 = has1 ? g_pre[n1 * STRIDE + lane] : 0.f;
        float h0 = fmaxf(fmaf(p0, A, B), 0.f);
        float h1 = fmaxf(fmaf(p1, A, B), 0.f);
        float m0 = 0.f, m1 = 0.f;
#pragma unroll
        for (int k = 0; k < D; k++) {
            float w = wcol[k];
            m0 = fmaf(__shfl_sync(0xffffffffu, h0, k), w, m0);
            m1 = fmaf(__shfl_sync(0xffffffffu, h1, k), w, m1);
        }
        float t0 = 0.f, t1 = 0.f;
        if (lane < 12) {
            t0 = fmaxf(m0 + bmv, 0.f) * wm2;
            t1 = fmaxf(m1 + bmv, 0.f) * wm2;
        }
#pragma unroll
        for (int o = 16; o > 0; o >>= 1) {
            t0 += __shfl_down_sync(0xffffffffu, t0, o);
            t1 += __shfl_down_sync(0xffffffffu, t1, o);
        }
        if (lane == 0) {
            out[n0] = 1.f / (1.f + __expf(-(t0 + bm2v)));
            g_cur[n0] = 0;
            if (has1) {
                out[n1] = 1.f / (1.f + __expf(-(t1 + bm2v)));
                g_cur[n1] = 0;
            }
        }
    }
}

// ---------------- launch -----------------------------------------------------

extern "C" void kernel_launch(void* const* d_in, const int* in_sizes, int n_in,
                              void* d_out, int out_size) {
    const int*   x   = (const int*)d_in[0];
    const int*   ei  = (const int*)d_in[1];
    const float* emb = (const float*)d_in[2];
    const float* W1  = (const float*)d_in[3];
    const float* b1  = (const float*)d_in[4];
    const float* g1  = (const float*)d_in[5];
    const float* be1 = (const float*)d_in[6];
    const float* W2  = (const float*)d_in[7];
    const float* b2  = (const float*)d_in[8];
    const float* g2  = (const float*)d_in[9];
    const float* be2 = (const float*)d_in[10];
    const float* Wm1 = (const float*)d_in[11];
    const float* bm1 = (const float*)d_in[12];
    const float* Wm2 = (const float*)d_in[13];
    const float* bm2 = (const float*)d_in[14];
    float* out = (float*)d_out;

    int n = in_sizes[0];
    int E = in_sizes[1] / 2;
    float inv_n = 1.f / (float)n;

    int FB = ((E + 7) / 8 + 255) / 256;    // fill blocks (8 edges/thread)
    int fusedBlocks = FB + NB1;
    int sclBlocks = (n * 8 + 255) / 256;

    k_fill_node1<<<fusedBlocks, 256>>>(ei, E, x, emb, W1, n, FB);
    k_scale<<<sclBlocks, 256>>>(n);
    k_agg<<<1184, 256>>>(b1, 0, n);

    k_node2<<<1184, 256>>>(W2, g1, be1, 0, inv_n, n);
    k_agg<<<1184, 256>>>(b2, 128, n);

    k_final<<<1184, 256>>>(g2, be2, Wm1, bm1, Wm2, bm2, out, 128, inv_n, n);
}